// round 14
// baseline (speedup 1.0000x reference)
#include <cuda_runtime.h>
#include <cuda_fp16.h>
#include <math.h>
#include <stdint.h>

#define BATCH 4
#define SEQ   2048
#define DMODEL 2048
#define NHEAD 16
#define HDIM  128
#define MROWS (BATCH * SEQ)   // 8192

// Scratch (allocation-free rule: __device__ globals)
__device__ __half g_q[(size_t)MROWS * DMODEL];
__device__ __half g_k[(size_t)MROWS * DMODEL];
__device__ __half g_v[(size_t)MROWS * DMODEL];
__device__ __half g_ctx[(size_t)MROWS * DMODEL];
__device__ __half g_xh[(size_t)MROWS * DMODEL];
__device__ __half g_wqh[(size_t)DMODEL * DMODEL];
__device__ __half g_wkh[(size_t)DMODEL * DMODEL];
__device__ __half g_wvh[(size_t)DMODEL * DMODEL];
__device__ __half g_woh[(size_t)DMODEL * DMODEL];

// ---------------------------------------------------------------------------
// helpers
// ---------------------------------------------------------------------------
__device__ __forceinline__ uint32_t h2pack(float lo, float hi) {
    __half2 h = __floats2half2_rn(lo, hi);
    return *reinterpret_cast<uint32_t*>(&h);
}

__device__ __forceinline__ void mma16(float* d, const uint32_t* a, const uint32_t* b) {
    asm volatile(
        "mma.sync.aligned.m16n8k16.row.col.f32.f16.f16.f32 "
        "{%0,%1,%2,%3}, {%4,%5,%6,%7}, {%8,%9}, {%0,%1,%2,%3};\n"
        : "+f"(d[0]), "+f"(d[1]), "+f"(d[2]), "+f"(d[3])
        : "r"(a[0]), "r"(a[1]), "r"(a[2]), "r"(a[3]),
          "r"(b[0]), "r"(b[1]));
}

__device__ __forceinline__ void ldsm4(uint32_t* r, uint32_t addr) {
    asm volatile("ldmatrix.sync.aligned.m8n8.x4.shared.b16 {%0,%1,%2,%3}, [%4];"
                 : "=r"(r[0]), "=r"(r[1]), "=r"(r[2]), "=r"(r[3]) : "r"(addr));
}
__device__ __forceinline__ void ldsm4t(uint32_t* r, uint32_t addr) {
    asm volatile("ldmatrix.sync.aligned.m8n8.x4.trans.shared.b16 {%0,%1,%2,%3}, [%4];"
                 : "=r"(r[0]), "=r"(r[1]), "=r"(r[2]), "=r"(r[3]) : "r"(addr));
}

__device__ __forceinline__ void cpa16(uint32_t sa, const void* g) {
    asm volatile("cp.async.cg.shared.global [%0], [%1], 16;\n" :: "r"(sa), "l"(g));
}
__device__ __forceinline__ void cpa_commit() {
    asm volatile("cp.async.commit_group;\n");
}
template <int N>
__device__ __forceinline__ void cpa_wait() {
    asm volatile("cp.async.wait_group %0;\n" :: "n"(N));
}
__device__ __forceinline__ uint32_t smem_u32(const void* p) {
    return (uint32_t)__cvta_generic_to_shared(p);
}

// ---------------------------------------------------------------------------
// one-shot f32 -> f16 conversion (n % 4 == 0)
// ---------------------------------------------------------------------------
__global__ __launch_bounds__(256) void f2h_kernel(
    const float* __restrict__ in, __half* __restrict__ out, int n)
{
    int i = (blockIdx.x * 256 + threadIdx.x) * 4;
    if (i < n) {
        float4 v = *(const float4*)(in + i);
        uint2 u = make_uint2(h2pack(v.x, v.y), h2pack(v.z, v.w));
        *(uint2*)(out + i) = u;
    }
}

// ---------------------------------------------------------------------------
// fp16 GEMM:  C[M,N] = A[M,K] @ W[N,K]^T + bias[N]  (opt *scale)
// CTA tile 128(M) x 64(N), 128 threads = 4 warps (2m x 2n), warp tile 64x32
// (round-10 fragment maps, unchanged). K-chunk 32, 3-stage cp.async pipeline
// (A 10KB + B 5KB per stage = 45KB total) -> OCCUPANCY 4: 16 warps/SM with
// 4-way cross-CTA overlap at every barrier/wait (vs 2-way in round 10).
// Smem stride 20 words: ldmatrix 8-lane phases are bank permutations.
// ---------------------------------------------------------------------------
#define GSTR  20
#define AWRD  (128 * GSTR)            // A words per stage (2560)
#define BWRD  (64 * GSTR)             // B words per stage (1280)
#define STG_B ((AWRD + BWRD) * 4)     // bytes per stage (15360)
#define GNST  3

template <bool HALF_OUT>
__global__ __launch_bounds__(128, 4) void gemm_hh(
    const __half* __restrict__ A, const __half* __restrict__ W,
    const float* __restrict__ bias, void* __restrict__ Cv,
    float scale, int M, int N, int K)
{
    extern __shared__ uint32_t gsm[];
    const uint32_t sb = smem_u32(gsm);

    const int tid = threadIdx.x;
    const int l  = tid & 31, w = tid >> 5;
    const int wm = w >> 1, wn = w & 1, lg = l >> 2, lt = l & 3;

    // staging: thread t -> A row t (full 64B); B row t>>1, 32B half (t&1)
    const int br = tid >> 1, bseg = tid & 1;
    const __half* Ap = A + (size_t)(blockIdx.y * 128 + tid) * K;
    const __half* Wp = W + (size_t)(blockIdx.x * 64 + br) * K + bseg * 16;
    const uint32_t a_sdst = (tid * GSTR) * 4;
    const uint32_t b_sdst = (AWRD + br * GSTR + bseg * 8) * 4;

    auto issue = [&](int c) {
        const uint32_t st = sb + (c % 3) * STG_B;
        const __half* ag = Ap + c * 32;
        const __half* wg = Wp + c * 32;
        cpa16(st + a_sdst,      ag);
        cpa16(st + a_sdst + 16, ag + 8);
        cpa16(st + a_sdst + 32, ag + 16);
        cpa16(st + a_sdst + 48, ag + 24);
        cpa16(st + b_sdst,      wg);
        cpa16(st + b_sdst + 16, wg + 8);
        cpa_commit();
    };

    const uint32_t a_off = ((wm * 64 + (l & 7) + ((l >> 3) & 1) * 8) * GSTR
                           + (l >> 4) * 4) * 4;
    const uint32_t b_off = (AWRD + (wn * 32 + (l >> 4) * 8 + (l & 7)) * GSTR
                           + ((l >> 3) & 1) * 4) * 4;

    float acc[4][4][4];
#pragma unroll
    for (int mi = 0; mi < 4; mi++)
#pragma unroll
        for (int nj = 0; nj < 4; nj++)
#pragma unroll
            for (int r = 0; r < 4; r++) acc[mi][nj][r] = 0.0f;

    const int NCH = K / 32;   // 64
    issue(0); issue(1);

    for (int c = 0; c < NCH; c++) {
        if (c + 1 < NCH) cpa_wait<1>();
        else             cpa_wait<0>();
        __syncthreads();
        if (c + 2 < NCH) issue(c + 2);

        const uint32_t st = sb + (c % 3) * STG_B;
#pragma unroll
        for (int ks = 0; ks < 2; ks++) {
            uint32_t af[4][4], bf[2][4];
#pragma unroll
            for (int mi = 0; mi < 4; mi++)
                ldsm4(af[mi], st + a_off + (mi * 16 * GSTR + ks * 8) * 4);
#pragma unroll
            for (int j2 = 0; j2 < 2; j2++)
                ldsm4(bf[j2], st + b_off + (j2 * 16 * GSTR + ks * 8) * 4);
#pragma unroll
            for (int mi = 0; mi < 4; mi++)
#pragma unroll
                for (int nj = 0; nj < 4; nj++)
                    mma16(acc[mi][nj], af[mi], &bf[nj >> 1][(nj & 1) * 2]);
        }
    }

#pragma unroll
    for (int mi = 0; mi < 4; mi++) {
        int r = blockIdx.y * 128 + wm * 64 + mi * 16 + lg;
#pragma unroll
        for (int nj = 0; nj < 4; nj++) {
            int cc = blockIdx.x * 64 + wn * 32 + nj * 8 + lt * 2;
            float b0 = bias[cc], b1 = bias[cc + 1];
            if (HALF_OUT) {
                __half* C = (__half*)Cv;
                *(__half2*)(C + (size_t)r * N + cc) =
                    __floats2half2_rn((acc[mi][nj][0] + b0) * scale,
                                      (acc[mi][nj][1] + b1) * scale);
                *(__half2*)(C + (size_t)(r + 8) * N + cc) =
                    __floats2half2_rn((acc[mi][nj][2] + b0) * scale,
                                      (acc[mi][nj][3] + b1) * scale);
            } else {
                float* C = (float*)Cv;
                *(float2*)(C + (size_t)r * N + cc) =
                    make_float2(acc[mi][nj][0] + b0, acc[mi][nj][1] + b1);
                *(float2*)(C + (size_t)(r + 8) * N + cc) =
                    make_float2(acc[mi][nj][2] + b0, acc[mi][nj][3] + b1);
            }
        }
    }
}

// ---------------------------------------------------------------------------
// FP16 flash attention (byte-identical to rounds 9/10 — 485us, known good).
// ---------------------------------------------------------------------------
#define ASTRD 68
#define NIT   (SEQ / 64)

__global__ __launch_bounds__(256, 2) void attn_h(
    const __half* __restrict__ Q, const __half* __restrict__ K,
    const __half* __restrict__ V, __half* __restrict__ O)
{
    extern __shared__ uint32_t sm[];
    const int tid = threadIdx.x;
    const int l = tid & 31, w = tid >> 5;
    const int lg = l >> 2, lt = l & 3;
    const int b = blockIdx.x >> 4, h = blockIdx.x & 15;
    const int q0 = blockIdx.y * 128;
    const int r0 = w * 16 + lg;

    const size_t base = (size_t)b * SEQ * DMODEL + (size_t)h * HDIM;

    const uint32_t qsh = smem_u32(sm);
    const uint32_t ksh = qsh + 128 * ASTRD * 4;
    const uint32_t vsh = ksh + 2 * 64 * ASTRD * 4;

    {
        int r = tid >> 1, half64 = (tid & 1);
        const __half* qg = Q + base + (size_t)(q0 + r) * DMODEL + half64 * 64;
        uint32_t d = qsh + (r * ASTRD + half64 * 32) * 4;
#pragma unroll
        for (int i = 0; i < 8; i++)
            cpa16(d + i * 16, qg + i * 8);
        cpa_commit();
    }

    const int vr = tid >> 2, vc = (tid & 3) * 4;

    auto issueK = [&](int kt, int buf) {
        const __half* g = K + base + (size_t)(kt * 64 + vr) * DMODEL + vc * 8;
        uint32_t d = ksh + buf * 64 * ASTRD * 4 + (vr * ASTRD + vc * 4) * 4;
#pragma unroll
        for (int i = 0; i < 4; i++) cpa16(d + i * 16, g + i * 8);
        cpa_commit();
    };
    auto issueV = [&](int kt, int buf) {
        const __half* g = V + base + (size_t)(kt * 64 + vr) * DMODEL + vc * 8;
        uint32_t d = vsh + buf * 64 * ASTRD * 4 + (vr * ASTRD + vc * 4) * 4;
#pragma unroll
        for (int i = 0; i < 4; i++) cpa16(d + i * 16, g + i * 8);
        cpa_commit();
    };

    issueK(0, 0);
    issueV(0, 0);

    const uint32_t q_off  = ((w * 16 + (l & 7) + ((l >> 3) & 1) * 8) * ASTRD
                            + (l >> 4) * 4) * 4;
    const uint32_t k_lane = (((l >> 4) * 8 + (l & 7)) * ASTRD
                            + ((l >> 3) & 1) * 4) * 4;
    const uint32_t v_lane = ((((l >> 3) & 1) * 8 + (l & 7)) * ASTRD
                            + (l >> 4) * 4) * 4;

    float o[16][4];
#pragma unroll
    for (int j = 0; j < 16; j++)
#pragma unroll
        for (int r = 0; r < 4; r++) o[j][r] = 0.0f;
    float m_lo = -INFINITY, m_hi = -INFINITY, l_lo = 0.0f, l_hi = 0.0f;

    for (int i = 0; i < NIT; i++) {
        const int kb = i & 1;
        if (i + 1 < NIT) { issueK(i + 1, kb ^ 1); cpa_wait<2>(); }
        else             { cpa_wait<1>(); }
        __syncthreads();

        const uint32_t ksb = ksh + kb * 64 * ASTRD * 4;
        float s[8][4];
#pragma unroll
        for (int j = 0; j < 8; j++)
#pragma unroll
            for (int r = 0; r < 4; r++) s[j][r] = 0.0f;
#pragma unroll
        for (int ks = 0; ks < 8; ks++) {
            uint32_t af[4];
            ldsm4(af, qsh + q_off + ks * 32);
#pragma unroll
            for (int j2 = 0; j2 < 4; j2++) {
                uint32_t bf[4];
                ldsm4(bf, ksb + k_lane + (j2 * 16 * ASTRD) * 4 + ks * 32);
                mma16(s[2 * j2], af, bf);
                mma16(s[2 * j2 + 1], af, bf + 2);
            }
        }

        float mlo = -INFINITY, mhi = -INFINITY;
#pragma unroll
        for (int j = 0; j < 8; j++) {
            mlo = fmaxf(mlo, fmaxf(s[j][0], s[j][1]));
            mhi = fmaxf(mhi, fmaxf(s[j][2], s[j][3]));
        }
        mlo = fmaxf(mlo, __shfl_xor_sync(0xffffffffu, mlo, 1));
        mlo = fmaxf(mlo, __shfl_xor_sync(0xffffffffu, mlo, 2));
        mhi = fmaxf(mhi, __shfl_xor_sync(0xffffffffu, mhi, 1));
        mhi = fmaxf(mhi, __shfl_xor_sync(0xffffffffu, mhi, 2));
        float mnl = fmaxf(m_lo, mlo), mnh = fmaxf(m_hi, mhi);
        float al = __expf(m_lo - mnl), ah = __expf(m_hi - mnh);

        float pl = 0.0f, ph = 0.0f;
#pragma unroll
        for (int j = 0; j < 8; j++) {
            s[j][0] = __expf(s[j][0] - mnl);
            s[j][1] = __expf(s[j][1] - mnl);
            s[j][2] = __expf(s[j][2] - mnh);
            s[j][3] = __expf(s[j][3] - mnh);
            pl += s[j][0] + s[j][1];
            ph += s[j][2] + s[j][3];
        }
        pl += __shfl_xor_sync(0xffffffffu, pl, 1);
        pl += __shfl_xor_sync(0xffffffffu, pl, 2);
        ph += __shfl_xor_sync(0xffffffffu, ph, 1);
        ph += __shfl_xor_sync(0xffffffffu, ph, 2);
        l_lo = l_lo * al + pl;
        l_hi = l_hi * ah + ph;
        m_lo = mnl; m_hi = mnh;
#pragma unroll
        for (int j = 0; j < 16; j++) {
            o[j][0] *= al; o[j][1] *= al;
            o[j][2] *= ah; o[j][3] *= ah;
        }

        if (i + 1 < NIT) { issueV(i + 1, kb ^ 1); cpa_wait<2>(); }
        else             { cpa_wait<0>(); }
        __syncthreads();

        const uint32_t vsb = vsh + kb * 64 * ASTRD * 4;
#pragma unroll
        for (int ks = 0; ks < 4; ks++) {
            uint32_t pa[4];
            pa[0] = h2pack(s[2 * ks][0],     s[2 * ks][1]);
            pa[1] = h2pack(s[2 * ks][2],     s[2 * ks][3]);
            pa[2] = h2pack(s[2 * ks + 1][0], s[2 * ks + 1][1]);
            pa[3] = h2pack(s[2 * ks + 1][2], s[2 * ks + 1][3]);
#pragma unroll
            for (int j2 = 0; j2 < 8; j2++) {
                uint32_t bf[4];
                ldsm4t(bf, vsb + v_lane + (ks * 16 * ASTRD) * 4 + j2 * 32);
                mma16(o[2 * j2], pa, bf);
                mma16(o[2 * j2 + 1], pa, bf + 2);
            }
        }
    }

    float il = 1.0f / l_lo, ih = 1.0f / l_hi;
    __half* orow0 = O + base + (size_t)(q0 + r0) * DMODEL;
    __half* orow1 = O + base + (size_t)(q0 + r0 + 8) * DMODEL;
#pragma unroll
    for (int j = 0; j < 16; j++) {
        int c = j * 8 + lt * 2;
        *(__half2*)(orow0 + c) = __floats2half2_rn(o[j][0] * il, o[j][1] * il);
        *(__half2*)(orow1 + c) = __floats2half2_rn(o[j][2] * ih, o[j][3] * ih);
    }
}

// ---------------------------------------------------------------------------
extern "C" void kernel_launch(void* const* d_in, const int* in_sizes, int n_in,
                              void* d_out, int out_size)
{
    const float* x  = (const float*)d_in[0];
    const float* Wq = (const float*)d_in[1];
    const float* bq = (const float*)d_in[2];
    const float* Wk = (const float*)d_in[3];
    const float* bk = (const float*)d_in[4];
    const float* Wv = (const float*)d_in[5];
    const float* bv = (const float*)d_in[6];
    const float* Wo = (const float*)d_in[7];
    const float* bo = (const float*)d_in[8];
    float* out = (float*)d_out;

    __half *qp, *kp, *vp, *cp, *xh, *wqh, *wkh, *wvh, *woh;
    cudaGetSymbolAddress((void**)&qp,  g_q);
    cudaGetSymbolAddress((void**)&kp,  g_k);
    cudaGetSymbolAddress((void**)&vp,  g_v);
    cudaGetSymbolAddress((void**)&cp,  g_ctx);
    cudaGetSymbolAddress((void**)&xh,  g_xh);
    cudaGetSymbolAddress((void**)&wqh, g_wqh);
    cudaGetSymbolAddress((void**)&wkh, g_wkh);
    cudaGetSymbolAddress((void**)&wvh, g_wvh);
    cudaGetSymbolAddress((void**)&woh, g_woh);

    const int gemm_smem = GNST * STG_B;   // 46080 B
    const int attn_smem = (128 * ASTRD + 2 * 64 * ASTRD + 2 * 64 * ASTRD) * 4; // 104448 B
    cudaFuncSetAttribute(gemm_hh<true>,  cudaFuncAttributeMaxDynamicSharedMemorySize, gemm_smem);
    cudaFuncSetAttribute(gemm_hh<false>, cudaFuncAttributeMaxDynamicSharedMemorySize, gemm_smem);
    cudaFuncSetAttribute(attn_h, cudaFuncAttributeMaxDynamicSharedMemorySize, attn_smem);

    // one-shot conversions
    const int nx = MROWS * DMODEL;          // 16,777,216
    const int nw = DMODEL * DMODEL;         //  4,194,304
    f2h_kernel<<<nx / 1024, 256>>>(x,  xh,  nx);
    f2h_kernel<<<nw / 1024, 256>>>(Wq, wqh, nw);
    f2h_kernel<<<nw / 1024, 256>>>(Wk, wkh, nw);
    f2h_kernel<<<nw / 1024, 256>>>(Wv, wvh, nw);
    f2h_kernel<<<nw / 1024, 256>>>(Wo, woh, nw);

    const float qscale = 0.08838834764831845f;   // 1/sqrt(128)

    dim3 gproj(DMODEL / 64, MROWS / 128);    // (32, 64)
    gemm_hh<true><<<gproj, 128, gemm_smem>>>(xh, wqh, bq, qp, qscale, MROWS, DMODEL, DMODEL);
    gemm_hh<true><<<gproj, 128, gemm_smem>>>(xh, wkh, bk, kp, 1.0f,   MROWS, DMODEL, DMODEL);
    gemm_hh<true><<<gproj, 128, gemm_smem>>>(xh, wvh, bv, vp, 1.0f,   MROWS, DMODEL, DMODEL);

    dim3 gattn(BATCH * NHEAD, SEQ / 128);    // (64, 16)
    attn_h<<<gattn, 256, attn_smem>>>(qp, kp, vp, cp);

    gemm_hh<false><<<gproj, 128, gemm_smem>>>(cp, woh, bo, out, 1.0f, MROWS, DMODEL, DMODEL);
}

// round 15
// speedup vs baseline: 1.2990x; 1.2990x over previous
#include <cuda_runtime.h>
#include <cuda_fp16.h>
#include <math.h>
#include <stdint.h>

#define BATCH 4
#define SEQ   2048
#define DMODEL 2048
#define NHEAD 16
#define HDIM  128
#define MROWS (BATCH * SEQ)   // 8192

// Scratch (allocation-free rule: __device__ globals)
__device__ __half g_q[(size_t)MROWS * DMODEL];
__device__ __half g_k[(size_t)MROWS * DMODEL];
__device__ __half g_v[(size_t)MROWS * DMODEL];
__device__ __half g_ctx[(size_t)MROWS * DMODEL];
__device__ __half g_xh[(size_t)MROWS * DMODEL];
__device__ __half g_wqh[(size_t)DMODEL * DMODEL];
__device__ __half g_wkh[(size_t)DMODEL * DMODEL];
__device__ __half g_wvh[(size_t)DMODEL * DMODEL];
__device__ __half g_woh[(size_t)DMODEL * DMODEL];

// ---------------------------------------------------------------------------
// helpers
// ---------------------------------------------------------------------------
__device__ __forceinline__ uint32_t h2pack(float lo, float hi) {
    __half2 h = __floats2half2_rn(lo, hi);
    return *reinterpret_cast<uint32_t*>(&h);
}

__device__ __forceinline__ void mma16(float* d, const uint32_t* a, const uint32_t* b) {
    asm volatile(
        "mma.sync.aligned.m16n8k16.row.col.f32.f16.f16.f32 "
        "{%0,%1,%2,%3}, {%4,%5,%6,%7}, {%8,%9}, {%0,%1,%2,%3};\n"
        : "+f"(d[0]), "+f"(d[1]), "+f"(d[2]), "+f"(d[3])
        : "r"(a[0]), "r"(a[1]), "r"(a[2]), "r"(a[3]),
          "r"(b[0]), "r"(b[1]));
}

__device__ __forceinline__ void ldsm4(uint32_t* r, uint32_t addr) {
    asm volatile("ldmatrix.sync.aligned.m8n8.x4.shared.b16 {%0,%1,%2,%3}, [%4];"
                 : "=r"(r[0]), "=r"(r[1]), "=r"(r[2]), "=r"(r[3]) : "r"(addr));
}
__device__ __forceinline__ void ldsm4t(uint32_t* r, uint32_t addr) {
    asm volatile("ldmatrix.sync.aligned.m8n8.x4.trans.shared.b16 {%0,%1,%2,%3}, [%4];"
                 : "=r"(r[0]), "=r"(r[1]), "=r"(r[2]), "=r"(r[3]) : "r"(addr));
}

__device__ __forceinline__ void cpa16(uint32_t sa, const void* g) {
    asm volatile("cp.async.cg.shared.global [%0], [%1], 16;\n" :: "r"(sa), "l"(g));
}
__device__ __forceinline__ void cpa_commit() {
    asm volatile("cp.async.commit_group;\n");
}
template <int N>
__device__ __forceinline__ void cpa_wait() {
    asm volatile("cp.async.wait_group %0;\n" :: "n"(N));
}
__device__ __forceinline__ uint32_t smem_u32(const void* p) {
    return (uint32_t)__cvta_generic_to_shared(p);
}

// ---------------------------------------------------------------------------
// one-shot f32 -> f16 conversion (n % 4 == 0)
// ---------------------------------------------------------------------------
__global__ __launch_bounds__(256) void f2h_kernel(
    const float* __restrict__ in, __half* __restrict__ out, int n)
{
    int i = (blockIdx.x * 256 + threadIdx.x) * 4;
    if (i < n) {
        float4 v = *(const float4*)(in + i);
        uint2 u = make_uint2(h2pack(v.x, v.y), h2pack(v.z, v.w));
        *(uint2*)(out + i) = u;
    }
}

// ---------------------------------------------------------------------------
// fp16 GEMM (round-10 geometry, byte-identical per-CTA):
//   C[M,N] = A[M,K] @ W[N,K]^T + bias[N]   (opt *scale)
// CTA tile 128x128, 256 thr, warps 2(m)x4(n), warp tile 64x32, K-chunk 32,
// 4-stage cp.async pipeline (A 10KB + B 10KB per stage = 80KB), occ 2.
// blockIdx.z selects (W, bias, C, scale) -> QKV fused in ONE launch with
// unchanged per-CTA structure. Smem stride 20 words (bank-permutation safe).
// ---------------------------------------------------------------------------
#define GSTR  20
#define STG_W (128 * GSTR)            // words per operand per stage (2560)
#define STG_B (2 * STG_W * 4)         // bytes per stage (20480)
#define GNST  4

template <bool HALF_OUT>
__global__ __launch_bounds__(256, 2) void gemm_hh(
    const __half* __restrict__ A,
    const __half* __restrict__ W0, const __half* __restrict__ W1,
    const __half* __restrict__ W2,
    const float* __restrict__ b0, const float* __restrict__ b1,
    const float* __restrict__ b2,
    void* __restrict__ C0, void* __restrict__ C1, void* __restrict__ C2,
    float s0, int M, int N, int K)
{
    extern __shared__ uint32_t gsm[];
    const uint32_t sb = smem_u32(gsm);

    const int z = blockIdx.z;
    const __half* Wm   = (z == 0) ? W0 : (z == 1) ? W1 : W2;
    const float*  bias = (z == 0) ? b0 : (z == 1) ? b1 : b2;
    void* Cv = (z == 0) ? C0 : (z == 1) ? C1 : C2;
    const float scale = (z == 0) ? s0 : 1.0f;

    const int tid = threadIdx.x;
    const int l  = tid & 31, w = tid >> 5;
    const int wm = w >> 2, wn = w & 3, lg = l >> 2, lt = l & 3;

    // staging: thread t covers row t>>1, 32B half-row (t&1), for A and B
    const int ra = tid >> 1, hseg = tid & 1;
    const __half* Ap = A  + (size_t)(blockIdx.y * 128 + ra) * K + hseg * 16;
    const __half* Wp = Wm + (size_t)(blockIdx.x * 128 + ra) * K + hseg * 16;
    const uint32_t a_sdst = (ra * GSTR + hseg * 8) * 4;
    const uint32_t b_sdst = (STG_W + ra * GSTR + hseg * 8) * 4;

    auto issue = [&](int c) {
        const uint32_t st = sb + (c & 3) * STG_B;
        const __half* ag = Ap + c * 32;
        const __half* wg = Wp + c * 32;
        cpa16(st + a_sdst,      ag);
        cpa16(st + a_sdst + 16, ag + 8);
        cpa16(st + b_sdst,      wg);
        cpa16(st + b_sdst + 16, wg + 8);
        cpa_commit();
    };

    const uint32_t a_off = ((wm * 64 + (l & 7) + ((l >> 3) & 1) * 8) * GSTR
                           + (l >> 4) * 4) * 4;
    const uint32_t b_off = (STG_W + (wn * 32 + (l >> 4) * 8 + (l & 7)) * GSTR
                           + ((l >> 3) & 1) * 4) * 4;

    float acc[4][4][4];
#pragma unroll
    for (int mi = 0; mi < 4; mi++)
#pragma unroll
        for (int nj = 0; nj < 4; nj++)
#pragma unroll
            for (int r = 0; r < 4; r++) acc[mi][nj][r] = 0.0f;

    const int NCH = K / 32;
    issue(0); issue(1); issue(2);

    for (int c = 0; c < NCH; c++) {
        if (c + 2 < NCH)      cpa_wait<2>();
        else if (c + 1 < NCH) cpa_wait<1>();
        else                  cpa_wait<0>();
        __syncthreads();
        if (c + 3 < NCH) issue(c + 3);

        const uint32_t st = sb + (c & 3) * STG_B;
#pragma unroll
        for (int ks = 0; ks < 2; ks++) {
            uint32_t af[4][4], bf[2][4];
#pragma unroll
            for (int mi = 0; mi < 4; mi++)
                ldsm4(af[mi], st + a_off + (mi * 16 * GSTR + ks * 8) * 4);
#pragma unroll
            for (int j2 = 0; j2 < 2; j2++)
                ldsm4(bf[j2], st + b_off + (j2 * 16 * GSTR + ks * 8) * 4);
#pragma unroll
            for (int mi = 0; mi < 4; mi++)
#pragma unroll
                for (int nj = 0; nj < 4; nj++)
                    mma16(acc[mi][nj], af[mi], &bf[nj >> 1][(nj & 1) * 2]);
        }
    }

#pragma unroll
    for (int mi = 0; mi < 4; mi++) {
        int r = blockIdx.y * 128 + wm * 64 + mi * 16 + lg;
#pragma unroll
        for (int nj = 0; nj < 4; nj++) {
            int cc = blockIdx.x * 128 + wn * 32 + nj * 8 + lt * 2;
            float bb0 = bias[cc], bb1 = bias[cc + 1];
            if (HALF_OUT) {
                __half* C = (__half*)Cv;
                *(__half2*)(C + (size_t)r * N + cc) =
                    __floats2half2_rn((acc[mi][nj][0] + bb0) * scale,
                                      (acc[mi][nj][1] + bb1) * scale);
                *(__half2*)(C + (size_t)(r + 8) * N + cc) =
                    __floats2half2_rn((acc[mi][nj][2] + bb0) * scale,
                                      (acc[mi][nj][3] + bb1) * scale);
            } else {
                float* C = (float*)Cv;
                *(float2*)(C + (size_t)r * N + cc) =
                    make_float2(acc[mi][nj][0] + bb0, acc[mi][nj][1] + bb1);
                *(float2*)(C + (size_t)(r + 8) * N + cc) =
                    make_float2(acc[mi][nj][2] + bb0, acc[mi][nj][3] + bb1);
            }
        }
    }
}

// ---------------------------------------------------------------------------
// FP16 flash attention (byte-identical to rounds 9/10 — 485us, known good).
// ---------------------------------------------------------------------------
#define ASTRD 68
#define NIT   (SEQ / 64)

__global__ __launch_bounds__(256, 2) void attn_h(
    const __half* __restrict__ Q, const __half* __restrict__ K,
    const __half* __restrict__ V, __half* __restrict__ O)
{
    extern __shared__ uint32_t sm[];
    const int tid = threadIdx.x;
    const int l = tid & 31, w = tid >> 5;
    const int lg = l >> 2, lt = l & 3;
    const int b = blockIdx.x >> 4, h = blockIdx.x & 15;
    const int q0 = blockIdx.y * 128;
    const int r0 = w * 16 + lg;

    const size_t base = (size_t)b * SEQ * DMODEL + (size_t)h * HDIM;

    const uint32_t qsh = smem_u32(sm);
    const uint32_t ksh = qsh + 128 * ASTRD * 4;
    const uint32_t vsh = ksh + 2 * 64 * ASTRD * 4;

    {
        int r = tid >> 1, half64 = (tid & 1);
        const __half* qg = Q + base + (size_t)(q0 + r) * DMODEL + half64 * 64;
        uint32_t d = qsh + (r * ASTRD + half64 * 32) * 4;
#pragma unroll
        for (int i = 0; i < 8; i++)
            cpa16(d + i * 16, qg + i * 8);
        cpa_commit();
    }

    const int vr = tid >> 2, vc = (tid & 3) * 4;

    auto issueK = [&](int kt, int buf) {
        const __half* g = K + base + (size_t)(kt * 64 + vr) * DMODEL + vc * 8;
        uint32_t d = ksh + buf * 64 * ASTRD * 4 + (vr * ASTRD + vc * 4) * 4;
#pragma unroll
        for (int i = 0; i < 4; i++) cpa16(d + i * 16, g + i * 8);
        cpa_commit();
    };
    auto issueV = [&](int kt, int buf) {
        const __half* g = V + base + (size_t)(kt * 64 + vr) * DMODEL + vc * 8;
        uint32_t d = vsh + buf * 64 * ASTRD * 4 + (vr * ASTRD + vc * 4) * 4;
#pragma unroll
        for (int i = 0; i < 4; i++) cpa16(d + i * 16, g + i * 8);
        cpa_commit();
    };

    issueK(0, 0);
    issueV(0, 0);

    const uint32_t q_off  = ((w * 16 + (l & 7) + ((l >> 3) & 1) * 8) * ASTRD
                            + (l >> 4) * 4) * 4;
    const uint32_t k_lane = (((l >> 4) * 8 + (l & 7)) * ASTRD
                            + ((l >> 3) & 1) * 4) * 4;
    const uint32_t v_lane = ((((l >> 3) & 1) * 8 + (l & 7)) * ASTRD
                            + (l >> 4) * 4) * 4;

    float o[16][4];
#pragma unroll
    for (int j = 0; j < 16; j++)
#pragma unroll
        for (int r = 0; r < 4; r++) o[j][r] = 0.0f;
    float m_lo = -INFINITY, m_hi = -INFINITY, l_lo = 0.0f, l_hi = 0.0f;

    for (int i = 0; i < NIT; i++) {
        const int kb = i & 1;
        if (i + 1 < NIT) { issueK(i + 1, kb ^ 1); cpa_wait<2>(); }
        else             { cpa_wait<1>(); }
        __syncthreads();

        const uint32_t ksb = ksh + kb * 64 * ASTRD * 4;
        float s[8][4];
#pragma unroll
        for (int j = 0; j < 8; j++)
#pragma unroll
            for (int r = 0; r < 4; r++) s[j][r] = 0.0f;
#pragma unroll
        for (int ks = 0; ks < 8; ks++) {
            uint32_t af[4];
            ldsm4(af, qsh + q_off + ks * 32);
#pragma unroll
            for (int j2 = 0; j2 < 4; j2++) {
                uint32_t bf[4];
                ldsm4(bf, ksb + k_lane + (j2 * 16 * ASTRD) * 4 + ks * 32);
                mma16(s[2 * j2], af, bf);
                mma16(s[2 * j2 + 1], af, bf + 2);
            }
        }

        float mlo = -INFINITY, mhi = -INFINITY;
#pragma unroll
        for (int j = 0; j < 8; j++) {
            mlo = fmaxf(mlo, fmaxf(s[j][0], s[j][1]));
            mhi = fmaxf(mhi, fmaxf(s[j][2], s[j][3]));
        }
        mlo = fmaxf(mlo, __shfl_xor_sync(0xffffffffu, mlo, 1));
        mlo = fmaxf(mlo, __shfl_xor_sync(0xffffffffu, mlo, 2));
        mhi = fmaxf(mhi, __shfl_xor_sync(0xffffffffu, mhi, 1));
        mhi = fmaxf(mhi, __shfl_xor_sync(0xffffffffu, mhi, 2));
        float mnl = fmaxf(m_lo, mlo), mnh = fmaxf(m_hi, mhi);
        float al = __expf(m_lo - mnl), ah = __expf(m_hi - mnh);

        float pl = 0.0f, ph = 0.0f;
#pragma unroll
        for (int j = 0; j < 8; j++) {
            s[j][0] = __expf(s[j][0] - mnl);
            s[j][1] = __expf(s[j][1] - mnl);
            s[j][2] = __expf(s[j][2] - mnh);
            s[j][3] = __expf(s[j][3] - mnh);
            pl += s[j][0] + s[j][1];
            ph += s[j][2] + s[j][3];
        }
        pl += __shfl_xor_sync(0xffffffffu, pl, 1);
        pl += __shfl_xor_sync(0xffffffffu, pl, 2);
        ph += __shfl_xor_sync(0xffffffffu, ph, 1);
        ph += __shfl_xor_sync(0xffffffffu, ph, 2);
        l_lo = l_lo * al + pl;
        l_hi = l_hi * ah + ph;
        m_lo = mnl; m_hi = mnh;
#pragma unroll
        for (int j = 0; j < 16; j++) {
            o[j][0] *= al; o[j][1] *= al;
            o[j][2] *= ah; o[j][3] *= ah;
        }

        if (i + 1 < NIT) { issueV(i + 1, kb ^ 1); cpa_wait<2>(); }
        else             { cpa_wait<0>(); }
        __syncthreads();

        const uint32_t vsb = vsh + kb * 64 * ASTRD * 4;
#pragma unroll
        for (int ks = 0; ks < 4; ks++) {
            uint32_t pa[4];
            pa[0] = h2pack(s[2 * ks][0],     s[2 * ks][1]);
            pa[1] = h2pack(s[2 * ks][2],     s[2 * ks][3]);
            pa[2] = h2pack(s[2 * ks + 1][0], s[2 * ks + 1][1]);
            pa[3] = h2pack(s[2 * ks + 1][2], s[2 * ks + 1][3]);
#pragma unroll
            for (int j2 = 0; j2 < 8; j2++) {
                uint32_t bf[4];
                ldsm4t(bf, vsb + v_lane + (ks * 16 * ASTRD) * 4 + j2 * 32);
                mma16(o[2 * j2], pa, bf);
                mma16(o[2 * j2 + 1], pa, bf + 2);
            }
        }
    }

    float il = 1.0f / l_lo, ih = 1.0f / l_hi;
    __half* orow0 = O + base + (size_t)(q0 + r0) * DMODEL;
    __half* orow1 = O + base + (size_t)(q0 + r0 + 8) * DMODEL;
#pragma unroll
    for (int j = 0; j < 16; j++) {
        int c = j * 8 + lt * 2;
        *(__half2*)(orow0 + c) = __floats2half2_rn(o[j][0] * il, o[j][1] * il);
        *(__half2*)(orow1 + c) = __floats2half2_rn(o[j][2] * ih, o[j][3] * ih);
    }
}

// ---------------------------------------------------------------------------
extern "C" void kernel_launch(void* const* d_in, const int* in_sizes, int n_in,
                              void* d_out, int out_size)
{
    const float* x  = (const float*)d_in[0];
    const float* Wq = (const float*)d_in[1];
    const float* bq = (const float*)d_in[2];
    const float* Wk = (const float*)d_in[3];
    const float* bk = (const float*)d_in[4];
    const float* Wv = (const float*)d_in[5];
    const float* bv = (const float*)d_in[6];
    const float* Wo = (const float*)d_in[7];
    const float* bo = (const float*)d_in[8];
    float* out = (float*)d_out;

    __half *qp, *kp, *vp, *cp, *xh, *wqh, *wkh, *wvh, *woh;
    cudaGetSymbolAddress((void**)&qp,  g_q);
    cudaGetSymbolAddress((void**)&kp,  g_k);
    cudaGetSymbolAddress((void**)&vp,  g_v);
    cudaGetSymbolAddress((void**)&cp,  g_ctx);
    cudaGetSymbolAddress((void**)&xh,  g_xh);
    cudaGetSymbolAddress((void**)&wqh, g_wqh);
    cudaGetSymbolAddress((void**)&wkh, g_wkh);
    cudaGetSymbolAddress((void**)&wvh, g_wvh);
    cudaGetSymbolAddress((void**)&woh, g_woh);

    const int gemm_smem = GNST * STG_B;   // 81920 B
    const int attn_smem = (128 * ASTRD + 2 * 64 * ASTRD + 2 * 64 * ASTRD) * 4; // 104448 B
    cudaFuncSetAttribute(gemm_hh<true>,  cudaFuncAttributeMaxDynamicSharedMemorySize, gemm_smem);
    cudaFuncSetAttribute(gemm_hh<false>, cudaFuncAttributeMaxDynamicSharedMemorySize, gemm_smem);
    cudaFuncSetAttribute(attn_h, cudaFuncAttributeMaxDynamicSharedMemorySize, attn_smem);

    // one-shot conversions
    const int nx = MROWS * DMODEL;          // 16,777,216
    const int nw = DMODEL * DMODEL;         //  4,194,304
    f2h_kernel<<<nx / 1024, 256>>>(x,  xh,  nx);
    f2h_kernel<<<nw / 1024, 256>>>(Wq, wqh, nw);
    f2h_kernel<<<nw / 1024, 256>>>(Wk, wkh, nw);
    f2h_kernel<<<nw / 1024, 256>>>(Wv, wvh, nw);
    f2h_kernel<<<nw / 1024, 256>>>(Wo, woh, nw);

    const float qscale = 0.08838834764831845f;   // 1/sqrt(128)

    // fused QKV: grid.z selects weight/bias/output; per-CTA code == round 10
    dim3 gqkv(DMODEL / 128, MROWS / 128, 3);   // (16, 64, 3)
    gemm_hh<true><<<gqkv, 256, gemm_smem>>>(
        xh, wqh, wkh, wvh, bq, bk, bv, qp, kp, vp,
        qscale, MROWS, DMODEL, DMODEL);

    dim3 gattn(BATCH * NHEAD, SEQ / 128);      // (64, 16)
    attn_h<<<gattn, 256, attn_smem>>>(qp, kp, vp, cp);

    dim3 gout(DMODEL / 128, MROWS / 128, 1);   // (16, 64, 1)
    gemm_hh<false><<<gout, 256, gemm_smem>>>(
        cp, woh, woh, woh, bo, bo, bo, out, out, out,
        1.0f, MROWS, DMODEL, DMODEL);
}